// round 2
// baseline (speedup 1.0000x reference)
#include <cuda_runtime.h>
#include <cuda_bf16.h>
#include <math.h>

// Problem constants
#define BB 64
#define SS 128
#define CC 32
#define DD 512
#define VV 20000
#define BS (BB*SS)          // 8192
#define G4D (4*DD)          // 2048

// ---------------- device scratch (allocation-free rule: __device__ globals) ----
__device__ float g_x[BS*DD];        // 16 MB   visit embeddings summed
__device__ float g_tf[BS*DD];       // 16 MB   time features
__device__ float g_ux[(size_t)BS*G4D]; // 64 MB input projection
__device__ float g_h[2][BB*DD];     // ping-pong hidden
__device__ float g_c[2][BB*DD];     // ping-pong cell
__device__ float g_hs[(size_t)BB*SS*DD]; // 16 MB all hidden states

// ---------------- f32x2 packed helpers (Blackwell) ----------------------------
__device__ __forceinline__ unsigned long long ffma2(unsigned long long a,
                                                    unsigned long long b,
                                                    unsigned long long c) {
    unsigned long long d;
    asm("fma.rn.f32x2 %0, %1, %2, %3;" : "=l"(d) : "l"(a), "l"(b), "l"(c));
    return d;
}
__device__ __forceinline__ unsigned long long pack2(float lo, float hi) {
    unsigned long long r;
    asm("mov.b64 %0, {%1, %2};" : "=l"(r) : "f"(lo), "f"(hi));
    return r;
}
__device__ __forceinline__ float2 unpack2(unsigned long long v) {
    float2 r;
    asm("mov.b64 {%0, %1}, %2;" : "=f"(r.x), "=f"(r.y) : "l"(v));
    return r;
}
union F4U { float4 f; unsigned long long u[2]; };

__device__ __forceinline__ float sigmoidf_(float x) { return 1.0f / (1.0f + expf(-x)); }

// ---------------- kernel: zero h0/c0 ------------------------------------------
__global__ void k_zero() {
    int i = blockIdx.x * blockDim.x + threadIdx.x;
    if (i < BB*DD) { g_h[0][i] = 0.0f; g_c[0][i] = 0.0f; }
}

// ---------------- kernel: gather + sum embeddings ------------------------------
// one block per (b,s): smem indices, each thread one float4 chunk of D
__global__ __launch_bounds__(128) void k_gather(const float* __restrict__ emb,
                                                const int* __restrict__ seqs) {
    int bs = blockIdx.x;
    __shared__ int sidx[CC];
    if (threadIdx.x < CC) sidx[threadIdx.x] = seqs[bs*CC + threadIdx.x];
    __syncthreads();
    int d4 = threadIdx.x;  // 0..127
    float4 acc = make_float4(0.f, 0.f, 0.f, 0.f);
#pragma unroll 8
    for (int c = 0; c < CC; c++) {
        const float4* row = (const float4*)(emb + (size_t)sidx[c] * DD);
        float4 v = __ldg(row + d4);
        acc.x += v.x; acc.y += v.y; acc.z += v.z; acc.w += v.w;
    }
    ((float4*)(g_x + (size_t)bs * DD))[d4] = acc;
}

// ---------------- kernel: time feature ----------------------------------------
// grid 128: block -> (b = bx>>1, s-half). 512 threads = one d each.
// time_w row cached in registers (64 floats, fully unrolled).
__global__ __launch_bounds__(512) void k_tf(const float* __restrict__ tstep,
                                            const float* __restrict__ selw,
                                            const float* __restrict__ selb,
                                            const float* __restrict__ timew,
                                            const float* __restrict__ timeb) {
    int b  = blockIdx.x >> 1;
    int s0 = (blockIdx.x & 1) * 64;
    int d  = threadIdx.x;
    float tw[64];
    const float4* twp = (const float4*)(timew + (size_t)d * 64);
#pragma unroll
    for (int i = 0; i < 16; i++) {
        float4 v = __ldg(twp + i);
        tw[i*4+0] = v.x; tw[i*4+1] = v.y; tw[i*4+2] = v.z; tw[i*4+3] = v.w;
    }
    float tb = timeb[d];
    __shared__ float feat[64];
    for (int si = 0; si < 64; si++) {
        int s = s0 + si;
        if (d < 64) {
            float t = tstep[b*SS + s] * (1.0f / 180.0f);
            float v = t * selw[d] + selb[d];
            feat[d] = 1.0f - tanhf(v * v);
        }
        __syncthreads();
        float acc = tb;
#pragma unroll
        for (int k = 0; k < 64; k++) acc += feat[k] * tw[k];
        g_tf[((size_t)b*SS + s) * DD + d] = acc;
        __syncthreads();
    }
}

// ---------------- kernel: ux = x @ U^T + Ub  (SGEMM 8192x2048x512, f32x2) ------
#define TM 128
#define TN 128
#define TK 16
__global__ __launch_bounds__(256) void k_gemm_ux(const float* __restrict__ U,
                                                 const float* __restrict__ Ub) {
    __shared__ float As[2][TK][TM + 4];
    __shared__ float Bs[2][TK][TN + 4];
    int m0 = blockIdx.y * TM;
    int n0 = blockIdx.x * TN;
    int t = threadIdx.x;
    int lrow = t >> 2;          // 0..63
    int lcol = (t & 3) * 4;     // 0,4,8,12

    const float* Aptr = g_x + (size_t)(m0 + lrow) * DD + lcol;
    const float* Bptr = U   + (size_t)(n0 + lrow) * DD + lcol;

    float4 ra[2], rb[2];
    ra[0] = *(const float4*)(Aptr);
    ra[1] = *(const float4*)(Aptr + 64*DD);
    rb[0] = *(const float4*)(Bptr);
    rb[1] = *(const float4*)(Bptr + 64*DD);

    int tx = t & 15, ty = t >> 4;
    unsigned long long acc[8][4];
#pragma unroll
    for (int im = 0; im < 8; im++)
#pragma unroll
        for (int in = 0; in < 4; in++) acc[im][in] = 0ull;

    // store tile 0
#pragma unroll
    for (int i = 0; i < 2; i++) {
        int r = lrow + i*64;
        As[0][lcol+0][r] = ra[i].x; As[0][lcol+1][r] = ra[i].y;
        As[0][lcol+2][r] = ra[i].z; As[0][lcol+3][r] = ra[i].w;
        Bs[0][lcol+0][r] = rb[i].x; Bs[0][lcol+1][r] = rb[i].y;
        Bs[0][lcol+2][r] = rb[i].z; Bs[0][lcol+3][r] = rb[i].w;
    }
    __syncthreads();

    const int NT = DD / TK;  // 32
    for (int kt = 0; kt < NT; kt++) {
        if (kt < NT - 1) {
            const float* ap = Aptr + (kt+1)*TK;
            const float* bp = Bptr + (kt+1)*TK;
            ra[0] = *(const float4*)(ap);
            ra[1] = *(const float4*)(ap + 64*DD);
            rb[0] = *(const float4*)(bp);
            rb[1] = *(const float4*)(bp + 64*DD);
        }
        int buf = kt & 1;
#pragma unroll
        for (int k = 0; k < TK; k++) {
            float4 a0 = *(const float4*)&As[buf][k][ty*8];
            float4 a1 = *(const float4*)&As[buf][k][ty*8+4];
            F4U b0, b1;
            b0.f = *(const float4*)&Bs[buf][k][tx*8];
            b1.f = *(const float4*)&Bs[buf][k][tx*8+4];
            unsigned long long bb[4] = { b0.u[0], b0.u[1], b1.u[0], b1.u[1] };
            float av[8] = {a0.x,a0.y,a0.z,a0.w,a1.x,a1.y,a1.z,a1.w};
#pragma unroll
            for (int im = 0; im < 8; im++) {
                unsigned long long aa = pack2(av[im], av[im]);
#pragma unroll
                for (int in = 0; in < 4; in++) acc[im][in] = ffma2(aa, bb[in], acc[im][in]);
            }
        }
        if (kt < NT - 1) {
            __syncthreads();
            int nb = buf ^ 1;
#pragma unroll
            for (int i = 0; i < 2; i++) {
                int r = lrow + i*64;
                As[nb][lcol+0][r] = ra[i].x; As[nb][lcol+1][r] = ra[i].y;
                As[nb][lcol+2][r] = ra[i].z; As[nb][lcol+3][r] = ra[i].w;
                Bs[nb][lcol+0][r] = rb[i].x; Bs[nb][lcol+1][r] = rb[i].y;
                Bs[nb][lcol+2][r] = rb[i].z; Bs[nb][lcol+3][r] = rb[i].w;
            }
            __syncthreads();
        }
    }

    // epilogue: add bias, store
    float ub[8];
#pragma unroll
    for (int i = 0; i < 8; i++) ub[i] = Ub[n0 + tx*8 + i];
#pragma unroll
    for (int im = 0; im < 8; im++) {
        int m = m0 + ty*8 + im;
        float* Crow = g_ux + (size_t)m * G4D + n0 + tx*8;
#pragma unroll
        for (int in = 0; in < 4; in++) {
            float2 v = unpack2(acc[im][in]);
            Crow[in*2+0] = v.x + ub[in*2+0];
            Crow[in*2+1] = v.y + ub[in*2+1];
        }
    }
}

// ---------------- kernel: one recurrent step -----------------------------------
// grid 128 CTAs, each owns 4 j-columns x all 64 batch rows.
// smem: Wd rows (4x516), Wall rows (16x516), h/c chunks (64x68 each), reg prefetch.
#define WPAD 516
#define HPAD 68
#define STEP_SMEM ((4*WPAD + 16*WPAD + 64*HPAD + 64*HPAD) * 4)

__global__ __launch_bounds__(256) void k_step(int s,
        const float* __restrict__ Wall, const float* __restrict__ Wallb,
        const float* __restrict__ Wd,   const float* __restrict__ Wdb) {
    extern __shared__ float sm[];
    float* WD = sm;                       // 4*516
    float* WA = WD + 4*WPAD;              // 16*516
    float* HS = WA + 16*WPAD;             // 64*68
    float* CS = HS + 64*HPAD;             // 64*68

    const float* h_in = g_h[s & 1];
    const float* c_in = g_c[s & 1];
    float* h_out = g_h[(s + 1) & 1];
    float* c_out = g_c[(s + 1) & 1];

    int t  = threadIdx.x;
    int j0 = blockIdx.x * 4;

    // load weights into smem (padded rows)
#pragma unroll
    for (int i = 0; i < 2; i++) {
        int fi = t + i*256;               // 0..511 float4
        int jj = fi >> 7, k4 = fi & 127;
        float4 v = *(const float4*)(Wd + (size_t)(j0 + jj) * DD + k4*4);
        *(float4*)(WD + jj*WPAD + k4*4) = v;
    }
#pragma unroll
    for (int i = 0; i < 8; i++) {
        int fi = t + i*256;               // 0..2047 float4
        int r = fi >> 7, k4 = fi & 127;
        int g = r >> 2, jj = r & 3;
        float4 v = *(const float4*)(Wall + (size_t)(g*DD + j0 + jj) * DD + k4*4);
        *(float4*)(WA + r*WPAD + k4*4) = v;
    }

    // prefetch chunk 0 of h,c
    float4 ph[4], pc[4];
#pragma unroll
    for (int i = 0; i < 4; i++) {
        int fi = t + i*256; int bb = fi >> 4, k4 = fi & 15;
        ph[i] = *(const float4*)(h_in + bb*DD + k4*4);
        pc[i] = *(const float4*)(c_in + bb*DD + k4*4);
    }

    int b  = t >> 2;
    int jj = t & 3;
    unsigned long long accd = 0ull, acc[4] = {0ull, 0ull, 0ull, 0ull};
    const float* WDrow  = WD + jj*WPAD;
    const float* WArow0 = WA + (0*4 + jj)*WPAD;
    const float* WArow1 = WA + (1*4 + jj)*WPAD;
    const float* WArow2 = WA + (2*4 + jj)*WPAD;
    const float* WArow3 = WA + (3*4 + jj)*WPAD;
    const float* HSrow = HS + b*HPAD;
    const float* CSrow = CS + b*HPAD;

    for (int ch = 0; ch < 8; ch++) {
        __syncthreads();   // prev compute done (and weights visible on ch=0)
#pragma unroll
        for (int i = 0; i < 4; i++) {
            int fi = t + i*256; int bb = fi >> 4, k4 = fi & 15;
            *(float4*)(HS + bb*HPAD + k4*4) = ph[i];
            *(float4*)(CS + bb*HPAD + k4*4) = pc[i];
        }
        __syncthreads();
        if (ch < 7) {
#pragma unroll
            for (int i = 0; i < 4; i++) {
                int fi = t + i*256; int bb = fi >> 4, k4 = fi & 15;
                ph[i] = *(const float4*)(h_in + bb*DD + (ch+1)*64 + k4*4);
                pc[i] = *(const float4*)(c_in + bb*DD + (ch+1)*64 + k4*4);
            }
        }
        int wo = ch * 64;
#pragma unroll
        for (int k4 = 0; k4 < 16; k4++) {
            F4U hv, cv, wd, w0, w1, w2, w3;
            hv.f = *(const float4*)(HSrow + k4*4);
            cv.f = *(const float4*)(CSrow + k4*4);
            wd.f = *(const float4*)(WDrow  + wo + k4*4);
            w0.f = *(const float4*)(WArow0 + wo + k4*4);
            w1.f = *(const float4*)(WArow1 + wo + k4*4);
            w2.f = *(const float4*)(WArow2 + wo + k4*4);
            w3.f = *(const float4*)(WArow3 + wo + k4*4);
            accd   = ffma2(cv.u[0], wd.u[0], accd);
            accd   = ffma2(cv.u[1], wd.u[1], accd);
            acc[0] = ffma2(hv.u[0], w0.u[0], acc[0]);
            acc[0] = ffma2(hv.u[1], w0.u[1], acc[0]);
            acc[1] = ffma2(hv.u[0], w1.u[0], acc[1]);
            acc[1] = ffma2(hv.u[1], w1.u[1], acc[1]);
            acc[2] = ffma2(hv.u[0], w2.u[0], acc[2]);
            acc[2] = ffma2(hv.u[1], w2.u[1], acc[2]);
            acc[3] = ffma2(hv.u[0], w3.u[0], acc[3]);
            acc[3] = ffma2(hv.u[1], w3.u[1], acc[3]);
        }
    }

    // elementwise LSTM update for (b, j)
    int j = j0 + jj;
    size_t bsoff = ((size_t)b * SS + s);
    float2 vd = unpack2(accd);
    float cs1 = tanhf(vd.x + vd.y + Wdb[j]);
    float2 v0 = unpack2(acc[0]);
    float2 v1 = unpack2(acc[1]);
    float2 v2 = unpack2(acc[2]);
    float2 v3 = unpack2(acc[3]);
    const float* uxr = g_ux + bsoff * G4D;
    float fg = sigmoidf_(v0.x + v0.y + Wallb[0*DD + j] + uxr[0*DD + j]);
    float ig = sigmoidf_(v1.x + v1.y + Wallb[1*DD + j] + uxr[1*DD + j]);
    float og = sigmoidf_(v2.x + v2.y + Wallb[2*DD + j] + uxr[2*DD + j]);
    float ct = sigmoidf_(v3.x + v3.y + Wallb[3*DD + j] + uxr[3*DD + j]);

    float cprev = c_in[b*DD + j];
    float tfv   = g_tf[bsoff * DD + j];
    float cadj  = cprev + cs1 * (tfv - 1.0f);
    float cn    = fg * cadj + ig * ct;
    float hn    = og * tanhf(cn);
    c_out[b*DD + j] = cn;
    h_out[b*DD + j] = hn;
    g_hs[bsoff * DD + j] = hn;
}

// ---------------- kernel: max-pool over S + output head ------------------------
__global__ __launch_bounds__(512) void k_pool(const float* __restrict__ ow,
                                              const float* __restrict__ ob,
                                              float* __restrict__ out) {
    int b = blockIdx.x;
    int d = threadIdx.x;
    const float* p = g_hs + (size_t)b * SS * DD + d;
    float m = -3.0e38f;
#pragma unroll 8
    for (int s = 0; s < SS; s++) m = fmaxf(m, p[(size_t)s * DD]);
    float s0 = m * ow[d];
    float s1 = m * ow[DD + d];
    __shared__ float r0[512], r1[512];
    r0[d] = s0; r1[d] = s1;
    __syncthreads();
    for (int off = 256; off > 0; off >>= 1) {
        if (d < off) { r0[d] += r0[d + off]; r1[d] += r1[d + off]; }
        __syncthreads();
    }
    if (d == 0) {
        out[b*2 + 0] = r0[0] + ob[0];
        out[b*2 + 1] = r1[0] + ob[1];
    }
}

// ---------------- launch --------------------------------------------------------
extern "C" void kernel_launch(void* const* d_in, const int* in_sizes, int n_in,
                              void* d_out, int out_size) {
    const float* emb   = (const float*)d_in[0];
    const float* Wall  = (const float*)d_in[1];
    const float* Wallb = (const float*)d_in[2];
    const float* U     = (const float*)d_in[3];
    const float* Ub    = (const float*)d_in[4];
    const float* Wd    = (const float*)d_in[5];
    const float* Wdb   = (const float*)d_in[6];
    const float* selw  = (const float*)d_in[7];
    const float* selb  = (const float*)d_in[8];
    const float* timew = (const float*)d_in[9];
    const float* timeb = (const float*)d_in[10];
    const float* outw  = (const float*)d_in[11];
    const float* outb  = (const float*)d_in[12];
    const float* tstep = (const float*)d_in[13];
    const int*   seqs  = (const int*)d_in[14];
    float* out = (float*)d_out;

    cudaFuncSetAttribute(k_step, cudaFuncAttributeMaxDynamicSharedMemorySize, STEP_SMEM);

    k_zero<<<128, 256>>>();
    k_gather<<<BS, 128>>>(emb, seqs);
    k_tf<<<128, 512>>>(tstep, selw, selb, timew, timeb);
    k_gemm_ux<<<dim3(G4D/TN, BS/TM), 256>>>(U, Ub);
    for (int s = 0; s < SS; s++) {
        k_step<<<128, 256, STEP_SMEM>>>(s, Wall, Wallb, Wd, Wdb);
    }
    k_pool<<<BB, 512>>>(outw, outb, out);
}

// round 3
// speedup vs baseline: 1.0012x; 1.0012x over previous
#include <cuda_runtime.h>
#include <cuda_bf16.h>
#include <math.h>

// Problem constants
#define BB 64
#define SS 128
#define CC 32
#define DD 512
#define VV 20000
#define BS (BB*SS)          // 8192
#define G4D (4*DD)          // 2048

// ---------------- device scratch (allocation-free rule: __device__ globals) ----
__device__ float g_x[BS*DD];        // 16 MB   visit embeddings summed
__device__ float g_tf[BS*DD];       // 16 MB   time features
__device__ float g_ux[(size_t)BS*G4D]; // 64 MB input projection
__device__ float g_h[2][BB*DD];     // ping-pong hidden
__device__ float g_c[2][BB*DD];     // ping-pong cell
__device__ float g_hs[(size_t)BB*SS*DD]; // 16 MB all hidden states

// ---------------- f32x2 packed helpers (Blackwell) ----------------------------
__device__ __forceinline__ unsigned long long ffma2(unsigned long long a,
                                                    unsigned long long b,
                                                    unsigned long long c) {
    unsigned long long d;
    asm("fma.rn.f32x2 %0, %1, %2, %3;" : "=l"(d) : "l"(a), "l"(b), "l"(c));
    return d;
}
__device__ __forceinline__ unsigned long long pack2(float lo, float hi) {
    unsigned long long r;
    asm("mov.b64 %0, {%1, %2};" : "=l"(r) : "f"(lo), "f"(hi));
    return r;
}
__device__ __forceinline__ float2 unpack2(unsigned long long v) {
    float2 r;
    asm("mov.b64 {%0, %1}, %2;" : "=f"(r.x), "=f"(r.y) : "l"(v));
    return r;
}
union F4U { float4 f; unsigned long long u[2]; };

__device__ __forceinline__ float sigmoidf_(float x) { return 1.0f / (1.0f + expf(-x)); }

// ---------------- kernel: zero h0/c0 ------------------------------------------
__global__ void k_zero() {
    int i = blockIdx.x * blockDim.x + threadIdx.x;
    if (i < BB*DD) { g_h[0][i] = 0.0f; g_c[0][i] = 0.0f; }
}

// ---------------- kernel: gather + sum embeddings ------------------------------
// one block per (b,s): smem indices, each thread one float4 chunk of D
__global__ __launch_bounds__(128) void k_gather(const float* __restrict__ emb,
                                                const int* __restrict__ seqs) {
    int bs = blockIdx.x;
    __shared__ int sidx[CC];
    if (threadIdx.x < CC) sidx[threadIdx.x] = seqs[bs*CC + threadIdx.x];
    __syncthreads();
    int d4 = threadIdx.x;  // 0..127
    float4 acc = make_float4(0.f, 0.f, 0.f, 0.f);
#pragma unroll 8
    for (int c = 0; c < CC; c++) {
        const float4* row = (const float4*)(emb + (size_t)sidx[c] * DD);
        float4 v = __ldg(row + d4);
        acc.x += v.x; acc.y += v.y; acc.z += v.z; acc.w += v.w;
    }
    ((float4*)(g_x + (size_t)bs * DD))[d4] = acc;
}

// ---------------- kernel: time feature ----------------------------------------
// grid 128: block -> (b = bx>>1, s-half). 512 threads = one d each.
// time_w row cached in registers (64 floats, fully unrolled).
__global__ __launch_bounds__(512) void k_tf(const float* __restrict__ tstep,
                                            const float* __restrict__ selw,
                                            const float* __restrict__ selb,
                                            const float* __restrict__ timew,
                                            const float* __restrict__ timeb) {
    int b  = blockIdx.x >> 1;
    int s0 = (blockIdx.x & 1) * 64;
    int d  = threadIdx.x;
    float tw[64];
    const float4* twp = (const float4*)(timew + (size_t)d * 64);
#pragma unroll
    for (int i = 0; i < 16; i++) {
        float4 v = __ldg(twp + i);
        tw[i*4+0] = v.x; tw[i*4+1] = v.y; tw[i*4+2] = v.z; tw[i*4+3] = v.w;
    }
    float tb = timeb[d];
    __shared__ float feat[64];
    for (int si = 0; si < 64; si++) {
        int s = s0 + si;
        if (d < 64) {
            float t = tstep[b*SS + s] * (1.0f / 180.0f);
            float v = t * selw[d] + selb[d];
            feat[d] = 1.0f - tanhf(v * v);
        }
        __syncthreads();
        float acc = tb;
#pragma unroll
        for (int k = 0; k < 64; k++) acc += feat[k] * tw[k];
        g_tf[((size_t)b*SS + s) * DD + d] = acc;
        __syncthreads();
    }
}

// ---------------- kernel: ux = x @ U^T + Ub  (SGEMM 8192x2048x512, f32x2) ------
#define TM 128
#define TN 128
#define TK 16
__global__ __launch_bounds__(256) void k_gemm_ux(const float* __restrict__ U,
                                                 const float* __restrict__ Ub) {
    __shared__ float As[2][TK][TM + 4];
    __shared__ float Bs[2][TK][TN + 4];
    int m0 = blockIdx.y * TM;
    int n0 = blockIdx.x * TN;
    int t = threadIdx.x;
    int lrow = t >> 2;          // 0..63
    int lcol = (t & 3) * 4;     // 0,4,8,12

    const float* Aptr = g_x + (size_t)(m0 + lrow) * DD + lcol;
    const float* Bptr = U   + (size_t)(n0 + lrow) * DD + lcol;

    float4 ra[2], rb[2];
    ra[0] = *(const float4*)(Aptr);
    ra[1] = *(const float4*)(Aptr + 64*DD);
    rb[0] = *(const float4*)(Bptr);
    rb[1] = *(const float4*)(Bptr + 64*DD);

    int tx = t & 15, ty = t >> 4;
    unsigned long long acc[8][4];
#pragma unroll
    for (int im = 0; im < 8; im++)
#pragma unroll
        for (int in = 0; in < 4; in++) acc[im][in] = 0ull;

    // store tile 0
#pragma unroll
    for (int i = 0; i < 2; i++) {
        int r = lrow + i*64;
        As[0][lcol+0][r] = ra[i].x; As[0][lcol+1][r] = ra[i].y;
        As[0][lcol+2][r] = ra[i].z; As[0][lcol+3][r] = ra[i].w;
        Bs[0][lcol+0][r] = rb[i].x; Bs[0][lcol+1][r] = rb[i].y;
        Bs[0][lcol+2][r] = rb[i].z; Bs[0][lcol+3][r] = rb[i].w;
    }
    __syncthreads();

    const int NT = DD / TK;  // 32
    for (int kt = 0; kt < NT; kt++) {
        if (kt < NT - 1) {
            const float* ap = Aptr + (kt+1)*TK;
            const float* bp = Bptr + (kt+1)*TK;
            ra[0] = *(const float4*)(ap);
            ra[1] = *(const float4*)(ap + 64*DD);
            rb[0] = *(const float4*)(bp);
            rb[1] = *(const float4*)(bp + 64*DD);
        }
        int buf = kt & 1;
#pragma unroll
        for (int k = 0; k < TK; k++) {
            float4 a0 = *(const float4*)&As[buf][k][ty*8];
            float4 a1 = *(const float4*)&As[buf][k][ty*8+4];
            F4U b0, b1;
            b0.f = *(const float4*)&Bs[buf][k][tx*8];
            b1.f = *(const float4*)&Bs[buf][k][tx*8+4];
            unsigned long long bb[4] = { b0.u[0], b0.u[1], b1.u[0], b1.u[1] };
            float av[8] = {a0.x,a0.y,a0.z,a0.w,a1.x,a1.y,a1.z,a1.w};
#pragma unroll
            for (int im = 0; im < 8; im++) {
                unsigned long long aa = pack2(av[im], av[im]);
#pragma unroll
                for (int in = 0; in < 4; in++) acc[im][in] = ffma2(aa, bb[in], acc[im][in]);
            }
        }
        if (kt < NT - 1) {
            __syncthreads();
            int nb = buf ^ 1;
#pragma unroll
            for (int i = 0; i < 2; i++) {
                int r = lrow + i*64;
                As[nb][lcol+0][r] = ra[i].x; As[nb][lcol+1][r] = ra[i].y;
                As[nb][lcol+2][r] = ra[i].z; As[nb][lcol+3][r] = ra[i].w;
                Bs[nb][lcol+0][r] = rb[i].x; Bs[nb][lcol+1][r] = rb[i].y;
                Bs[nb][lcol+2][r] = rb[i].z; Bs[nb][lcol+3][r] = rb[i].w;
            }
            __syncthreads();
        }
    }

    // epilogue: add bias, store
    float ub[8];
#pragma unroll
    for (int i = 0; i < 8; i++) ub[i] = Ub[n0 + tx*8 + i];
#pragma unroll
    for (int im = 0; im < 8; im++) {
        int m = m0 + ty*8 + im;
        float* Crow = g_ux + (size_t)m * G4D + n0 + tx*8;
#pragma unroll
        for (int in = 0; in < 4; in++) {
            float2 v = unpack2(acc[im][in]);
            Crow[in*2+0] = v.x + ub[in*2+0];
            Crow[in*2+1] = v.y + ub[in*2+1];
        }
    }
}

// ---------------- kernel: one recurrent step -----------------------------------
// grid 128 CTAs, each owns 4 j-columns x all 64 batch rows.
// smem: Wd rows (4x516), Wall rows (16x516), h/c chunks (64x68 each), reg prefetch.
#define WPAD 516
#define HPAD 68
#define STEP_SMEM ((4*WPAD + 16*WPAD + 64*HPAD + 64*HPAD) * 4)

__global__ __launch_bounds__(256) void k_step(int s,
        const float* __restrict__ Wall, const float* __restrict__ Wallb,
        const float* __restrict__ Wd,   const float* __restrict__ Wdb) {
    extern __shared__ float sm[];
    float* WD = sm;                       // 4*516
    float* WA = WD + 4*WPAD;              // 16*516
    float* HS = WA + 16*WPAD;             // 64*68
    float* CS = HS + 64*HPAD;             // 64*68

    const float* h_in = g_h[s & 1];
    const float* c_in = g_c[s & 1];
    float* h_out = g_h[(s + 1) & 1];
    float* c_out = g_c[(s + 1) & 1];

    int t  = threadIdx.x;
    int j0 = blockIdx.x * 4;

    // load weights into smem (padded rows)
#pragma unroll
    for (int i = 0; i < 2; i++) {
        int fi = t + i*256;               // 0..511 float4
        int jj = fi >> 7, k4 = fi & 127;
        float4 v = *(const float4*)(Wd + (size_t)(j0 + jj) * DD + k4*4);
        *(float4*)(WD + jj*WPAD + k4*4) = v;
    }
#pragma unroll
    for (int i = 0; i < 8; i++) {
        int fi = t + i*256;               // 0..2047 float4
        int r = fi >> 7, k4 = fi & 127;
        int g = r >> 2, jj = r & 3;
        float4 v = *(const float4*)(Wall + (size_t)(g*DD + j0 + jj) * DD + k4*4);
        *(float4*)(WA + r*WPAD + k4*4) = v;
    }

    // prefetch chunk 0 of h,c
    float4 ph[4], pc[4];
#pragma unroll
    for (int i = 0; i < 4; i++) {
        int fi = t + i*256; int bb = fi >> 4, k4 = fi & 15;
        ph[i] = *(const float4*)(h_in + bb*DD + k4*4);
        pc[i] = *(const float4*)(c_in + bb*DD + k4*4);
    }

    int b  = t >> 2;
    int jj = t & 3;
    unsigned long long accd = 0ull, acc[4] = {0ull, 0ull, 0ull, 0ull};
    const float* WDrow  = WD + jj*WPAD;
    const float* WArow0 = WA + (0*4 + jj)*WPAD;
    const float* WArow1 = WA + (1*4 + jj)*WPAD;
    const float* WArow2 = WA + (2*4 + jj)*WPAD;
    const float* WArow3 = WA + (3*4 + jj)*WPAD;
    const float* HSrow = HS + b*HPAD;
    const float* CSrow = CS + b*HPAD;

    for (int ch = 0; ch < 8; ch++) {
        __syncthreads();   // prev compute done (and weights visible on ch=0)
#pragma unroll
        for (int i = 0; i < 4; i++) {
            int fi = t + i*256; int bb = fi >> 4, k4 = fi & 15;
            *(float4*)(HS + bb*HPAD + k4*4) = ph[i];
            *(float4*)(CS + bb*HPAD + k4*4) = pc[i];
        }
        __syncthreads();
        if (ch < 7) {
#pragma unroll
            for (int i = 0; i < 4; i++) {
                int fi = t + i*256; int bb = fi >> 4, k4 = fi & 15;
                ph[i] = *(const float4*)(h_in + bb*DD + (ch+1)*64 + k4*4);
                pc[i] = *(const float4*)(c_in + bb*DD + (ch+1)*64 + k4*4);
            }
        }
        int wo = ch * 64;
#pragma unroll
        for (int k4 = 0; k4 < 16; k4++) {
            F4U hv, cv, wd, w0, w1, w2, w3;
            hv.f = *(const float4*)(HSrow + k4*4);
            cv.f = *(const float4*)(CSrow + k4*4);
            wd.f = *(const float4*)(WDrow  + wo + k4*4);
            w0.f = *(const float4*)(WArow0 + wo + k4*4);
            w1.f = *(const float4*)(WArow1 + wo + k4*4);
            w2.f = *(const float4*)(WArow2 + wo + k4*4);
            w3.f = *(const float4*)(WArow3 + wo + k4*4);
            accd   = ffma2(cv.u[0], wd.u[0], accd);
            accd   = ffma2(cv.u[1], wd.u[1], accd);
            acc[0] = ffma2(hv.u[0], w0.u[0], acc[0]);
            acc[0] = ffma2(hv.u[1], w0.u[1], acc[0]);
            acc[1] = ffma2(hv.u[0], w1.u[0], acc[1]);
            acc[1] = ffma2(hv.u[1], w1.u[1], acc[1]);
            acc[2] = ffma2(hv.u[0], w2.u[0], acc[2]);
            acc[2] = ffma2(hv.u[1], w2.u[1], acc[2]);
            acc[3] = ffma2(hv.u[0], w3.u[0], acc[3]);
            acc[3] = ffma2(hv.u[1], w3.u[1], acc[3]);
        }
    }

    // elementwise LSTM update for (b, j)
    int j = j0 + jj;
    size_t bsoff = ((size_t)b * SS + s);
    float2 vd = unpack2(accd);
    float cs1 = tanhf(vd.x + vd.y + Wdb[j]);
    float2 v0 = unpack2(acc[0]);
    float2 v1 = unpack2(acc[1]);
    float2 v2 = unpack2(acc[2]);
    float2 v3 = unpack2(acc[3]);
    const float* uxr = g_ux + bsoff * G4D;
    float fg = sigmoidf_(v0.x + v0.y + Wallb[0*DD + j] + uxr[0*DD + j]);
    float ig = sigmoidf_(v1.x + v1.y + Wallb[1*DD + j] + uxr[1*DD + j]);
    float og = sigmoidf_(v2.x + v2.y + Wallb[2*DD + j] + uxr[2*DD + j]);
    float ct = sigmoidf_(v3.x + v3.y + Wallb[3*DD + j] + uxr[3*DD + j]);

    float cprev = c_in[b*DD + j];
    float tfv   = g_tf[bsoff * DD + j];
    float cadj  = cprev + cs1 * (tfv - 1.0f);
    float cn    = fg * cadj + ig * ct;
    float hn    = og * tanhf(cn);
    c_out[b*DD + j] = cn;
    h_out[b*DD + j] = hn;
    g_hs[bsoff * DD + j] = hn;
}

// ---------------- kernel: max-pool over S + output head ------------------------
__global__ __launch_bounds__(512) void k_pool(const float* __restrict__ ow,
                                              const float* __restrict__ ob,
                                              float* __restrict__ out) {
    int b = blockIdx.x;
    int d = threadIdx.x;
    const float* p = g_hs + (size_t)b * SS * DD + d;
    float m = -3.0e38f;
#pragma unroll 8
    for (int s = 0; s < SS; s++) m = fmaxf(m, p[(size_t)s * DD]);
    float s0 = m * ow[d];
    float s1 = m * ow[DD + d];
    __shared__ float r0[512], r1[512];
    r0[d] = s0; r1[d] = s1;
    __syncthreads();
    for (int off = 256; off > 0; off >>= 1) {
        if (d < off) { r0[d] += r0[d + off]; r1[d] += r1[d + off]; }
        __syncthreads();
    }
    if (d == 0) {
        out[b*2 + 0] = r0[0] + ob[0];
        out[b*2 + 1] = r1[0] + ob[1];
    }
}

// ---------------- launch --------------------------------------------------------
extern "C" void kernel_launch(void* const* d_in, const int* in_sizes, int n_in,
                              void* d_out, int out_size) {
    const float* emb   = (const float*)d_in[0];
    const float* Wall  = (const float*)d_in[1];
    const float* Wallb = (const float*)d_in[2];
    const float* U     = (const float*)d_in[3];
    const float* Ub    = (const float*)d_in[4];
    const float* Wd    = (const float*)d_in[5];
    const float* Wdb   = (const float*)d_in[6];
    const float* selw  = (const float*)d_in[7];
    const float* selb  = (const float*)d_in[8];
    const float* timew = (const float*)d_in[9];
    const float* timeb = (const float*)d_in[10];
    const float* outw  = (const float*)d_in[11];
    const float* outb  = (const float*)d_in[12];
    const float* tstep = (const float*)d_in[13];
    const int*   seqs  = (const int*)d_in[14];
    float* out = (float*)d_out;

    cudaFuncSetAttribute(k_step, cudaFuncAttributeMaxDynamicSharedMemorySize, STEP_SMEM);

    k_zero<<<128, 256>>>();
    k_gather<<<BS, 128>>>(emb, seqs);
    k_tf<<<128, 512>>>(tstep, selw, selb, timew, timeb);
    k_gemm_ux<<<dim3(G4D/TN, BS/TM), 256>>>(U, Ub);
    for (int s = 0; s < SS; s++) {
        k_step<<<128, 256, STEP_SMEM>>>(s, Wall, Wallb, Wd, Wdb);
    }
    k_pool<<<BB, 512>>>(outw, outb, out);
}

// round 4
// speedup vs baseline: 1.2386x; 1.2372x over previous
#include <cuda_runtime.h>
#include <cuda_bf16.h>
#include <math.h>

// Problem constants
#define BB 64
#define SS 128
#define CC 32
#define DD 512
#define VV 20000
#define BS (BB*SS)          // 8192
#define G4D (4*DD)          // 2048

// ---------------- device scratch (allocation-free rule: __device__ globals) ----
__device__ float g_x[BS*DD];           // 16 MB  visit embeddings summed
__device__ float g_tf[BS*DD];          // 16 MB  time features
__device__ float g_ux[(size_t)BS*G4D]; // 64 MB  input projection
__device__ float g_h[2][BB*DD];        // ping-pong hidden
__device__ float g_c[2][BB*DD];        // ping-pong cell
__device__ float g_hs[(size_t)BB*SS*DD]; // 16 MB all hidden states
__device__ unsigned g_bar;             // grid barrier counter

// ---------------- f32x2 packed helpers (Blackwell) ----------------------------
__device__ __forceinline__ unsigned long long ffma2(unsigned long long a,
                                                    unsigned long long b,
                                                    unsigned long long c) {
    unsigned long long d;
    asm("fma.rn.f32x2 %0, %1, %2, %3;" : "=l"(d) : "l"(a), "l"(b), "l"(c));
    return d;
}
__device__ __forceinline__ unsigned long long pack2(float lo, float hi) {
    unsigned long long r;
    asm("mov.b64 %0, {%1, %2};" : "=l"(r) : "f"(lo), "f"(hi));
    return r;
}
__device__ __forceinline__ float2 unpack2(unsigned long long v) {
    float2 r;
    asm("mov.b64 {%0, %1}, %2;" : "=f"(r.x), "=f"(r.y) : "l"(v));
    return r;
}
union F4U { float4 f; unsigned long long u[2]; };

__device__ __forceinline__ float sigmoidf_(float x) { return 1.0f / (1.0f + expf(-x)); }

// ---------------- kernel: zero h0/c0 + reset barrier ---------------------------
__global__ void k_zero() {
    int i = blockIdx.x * blockDim.x + threadIdx.x;
    if (i < BB*DD) { g_h[0][i] = 0.0f; g_c[0][i] = 0.0f; }
    if (i == 0) g_bar = 0u;
}

// ---------------- kernel: gather + sum embeddings ------------------------------
__global__ __launch_bounds__(128) void k_gather(const float* __restrict__ emb,
                                                const int* __restrict__ seqs) {
    int bs = blockIdx.x;
    __shared__ int sidx[CC];
    if (threadIdx.x < CC) sidx[threadIdx.x] = seqs[bs*CC + threadIdx.x];
    __syncthreads();
    int d4 = threadIdx.x;  // 0..127
    float4 acc = make_float4(0.f, 0.f, 0.f, 0.f);
#pragma unroll 8
    for (int c = 0; c < CC; c++) {
        const float4* row = (const float4*)(emb + (size_t)sidx[c] * DD);
        float4 v = __ldg(row + d4);
        acc.x += v.x; acc.y += v.y; acc.z += v.z; acc.w += v.w;
    }
    ((float4*)(g_x + (size_t)bs * DD))[d4] = acc;
}

// ---------------- kernel: time feature ----------------------------------------
__global__ __launch_bounds__(512) void k_tf(const float* __restrict__ tstep,
                                            const float* __restrict__ selw,
                                            const float* __restrict__ selb,
                                            const float* __restrict__ timew,
                                            const float* __restrict__ timeb) {
    int b  = blockIdx.x >> 1;
    int s0 = (blockIdx.x & 1) * 64;
    int d  = threadIdx.x;
    float tw[64];
    const float4* twp = (const float4*)(timew + (size_t)d * 64);
#pragma unroll
    for (int i = 0; i < 16; i++) {
        float4 v = __ldg(twp + i);
        tw[i*4+0] = v.x; tw[i*4+1] = v.y; tw[i*4+2] = v.z; tw[i*4+3] = v.w;
    }
    float tb = timeb[d];
    __shared__ float feat[64];
    for (int si = 0; si < 64; si++) {
        int s = s0 + si;
        if (d < 64) {
            float t = tstep[b*SS + s] * (1.0f / 180.0f);
            float v = t * selw[d] + selb[d];
            feat[d] = 1.0f - tanhf(v * v);
        }
        __syncthreads();
        float acc = tb;
#pragma unroll
        for (int k = 0; k < 64; k++) acc += feat[k] * tw[k];
        g_tf[((size_t)b*SS + s) * DD + d] = acc;
        __syncthreads();
    }
}

// ---------------- kernel: ux = x @ U^T + Ub  (SGEMM 8192x2048x512, f32x2) ------
#define TM 128
#define TN 128
#define TK 16
__global__ __launch_bounds__(256, 2) void k_gemm_ux(const float* __restrict__ U,
                                                    const float* __restrict__ Ub) {
    __shared__ float As[2][TK][TM + 4];
    __shared__ float Bs[2][TK][TN + 4];
    int m0 = blockIdx.y * TM;
    int n0 = blockIdx.x * TN;
    int t = threadIdx.x;
    int lrow = t >> 2;          // 0..63
    int lcol = (t & 3) * 4;     // 0,4,8,12

    const float* Aptr = g_x + (size_t)(m0 + lrow) * DD + lcol;
    const float* Bptr = U   + (size_t)(n0 + lrow) * DD + lcol;

    float4 ra[2], rb[2];
    ra[0] = *(const float4*)(Aptr);
    ra[1] = *(const float4*)(Aptr + 64*DD);
    rb[0] = *(const float4*)(Bptr);
    rb[1] = *(const float4*)(Bptr + 64*DD);

    int tx = t & 15, ty = t >> 4;
    unsigned long long acc[8][4];
#pragma unroll
    for (int im = 0; im < 8; im++)
#pragma unroll
        for (int in = 0; in < 4; in++) acc[im][in] = 0ull;

#pragma unroll
    for (int i = 0; i < 2; i++) {
        int r = lrow + i*64;
        As[0][lcol+0][r] = ra[i].x; As[0][lcol+1][r] = ra[i].y;
        As[0][lcol+2][r] = ra[i].z; As[0][lcol+3][r] = ra[i].w;
        Bs[0][lcol+0][r] = rb[i].x; Bs[0][lcol+1][r] = rb[i].y;
        Bs[0][lcol+2][r] = rb[i].z; Bs[0][lcol+3][r] = rb[i].w;
    }
    __syncthreads();

    const int NT = DD / TK;  // 32
    for (int kt = 0; kt < NT; kt++) {
        if (kt < NT - 1) {
            const float* ap = Aptr + (kt+1)*TK;
            const float* bp = Bptr + (kt+1)*TK;
            ra[0] = *(const float4*)(ap);
            ra[1] = *(const float4*)(ap + 64*DD);
            rb[0] = *(const float4*)(bp);
            rb[1] = *(const float4*)(bp + 64*DD);
        }
        int buf = kt & 1;
#pragma unroll
        for (int k = 0; k < TK; k++) {
            float4 a0 = *(const float4*)&As[buf][k][ty*8];
            float4 a1 = *(const float4*)&As[buf][k][ty*8+4];
            F4U b0, b1;
            b0.f = *(const float4*)&Bs[buf][k][tx*8];
            b1.f = *(const float4*)&Bs[buf][k][tx*8+4];
            unsigned long long bb[4] = { b0.u[0], b0.u[1], b1.u[0], b1.u[1] };
            float av[8] = {a0.x,a0.y,a0.z,a0.w,a1.x,a1.y,a1.z,a1.w};
#pragma unroll
            for (int im = 0; im < 8; im++) {
                unsigned long long aa = pack2(av[im], av[im]);
#pragma unroll
                for (int in = 0; in < 4; in++) acc[im][in] = ffma2(aa, bb[in], acc[im][in]);
            }
        }
        if (kt < NT - 1) {
            __syncthreads();
            int nb = buf ^ 1;
#pragma unroll
            for (int i = 0; i < 2; i++) {
                int r = lrow + i*64;
                As[nb][lcol+0][r] = ra[i].x; As[nb][lcol+1][r] = ra[i].y;
                As[nb][lcol+2][r] = ra[i].z; As[nb][lcol+3][r] = ra[i].w;
                Bs[nb][lcol+0][r] = rb[i].x; Bs[nb][lcol+1][r] = rb[i].y;
                Bs[nb][lcol+2][r] = rb[i].z; Bs[nb][lcol+3][r] = rb[i].w;
            }
            __syncthreads();
        }
    }

    float ub[8];
#pragma unroll
    for (int i = 0; i < 8; i++) ub[i] = Ub[n0 + tx*8 + i];
#pragma unroll
    for (int im = 0; im < 8; im++) {
        int m = m0 + ty*8 + im;
        float* Crow = g_ux + (size_t)m * G4D + n0 + tx*8;
#pragma unroll
        for (int in = 0; in < 4; in++) {
            float2 v = unpack2(acc[im][in]);
            Crow[in*2+0] = v.x + ub[in*2+0];
            Crow[in*2+1] = v.y + ub[in*2+1];
        }
    }
}

// ---------------- persistent recurrent kernel (all 128 steps) -------------------
// 128 CTAs, each owns 4 j-columns x all 64 batch rows. Weights live in smem for
// the whole sequence; h/c ping-pong through global (L2) with __ldcg; device-side
// phased grid barrier between steps.
#define WPAD 516
#define HPAD 68
#define STEP_SMEM ((4*WPAD + 16*WPAD + 64*HPAD + 64*HPAD) * 4)
#define NCTA 128

__global__ __launch_bounds__(256) void k_rnn(
        const float* __restrict__ Wall, const float* __restrict__ Wallb,
        const float* __restrict__ Wd,   const float* __restrict__ Wdb) {
    extern __shared__ float sm[];
    float* WD = sm;                       // 4*516
    float* WA = WD + 4*WPAD;              // 16*516
    float* HS = WA + 16*WPAD;             // 64*68
    float* CS = HS + 64*HPAD;             // 64*68

    int t  = threadIdx.x;
    int j0 = blockIdx.x * 4;

    // ---- load weights into smem ONCE (padded rows) ----
#pragma unroll
    for (int i = 0; i < 2; i++) {
        int fi = t + i*256;               // 0..511 float4
        int jj = fi >> 7, k4 = fi & 127;
        float4 v = *(const float4*)(Wd + (size_t)(j0 + jj) * DD + k4*4);
        *(float4*)(WD + jj*WPAD + k4*4) = v;
    }
#pragma unroll
    for (int i = 0; i < 8; i++) {
        int fi = t + i*256;               // 0..2047 float4
        int r = fi >> 7, k4 = fi & 127;
        int g = r >> 2, jj = r & 3;
        float4 v = *(const float4*)(Wall + (size_t)(g*DD + j0 + jj) * DD + k4*4);
        *(float4*)(WA + r*WPAD + k4*4) = v;
    }

    int b  = t >> 2;
    int jj = t & 3;
    int j  = j0 + jj;
    int cchunk = j0 >> 6;                 // which h/c chunk holds column j
    int cidx   = j & 63;

    // per-thread biases (constant over all steps)
    float wdb  = __ldg(Wdb + j);
    float wab0 = __ldg(Wallb + 0*DD + j);
    float wab1 = __ldg(Wallb + 1*DD + j);
    float wab2 = __ldg(Wallb + 2*DD + j);
    float wab3 = __ldg(Wallb + 3*DD + j);

    const float* WDrow  = WD + jj*WPAD;
    const float* WArow0 = WA + (0*4 + jj)*WPAD;
    const float* WArow1 = WA + (1*4 + jj)*WPAD;
    const float* WArow2 = WA + (2*4 + jj)*WPAD;
    const float* WArow3 = WA + (3*4 + jj)*WPAD;
    const float* HSrow  = HS + b*HPAD;
    const float* CSrow  = CS + b*HPAD;

    for (int s = 0; s < SS; s++) {
        const float* h_in = g_h[s & 1];
        const float* c_in = g_c[s & 1];
        float* h_out = g_h[(s + 1) & 1];
        float* c_out = g_c[(s + 1) & 1];
        size_t bsoff = ((size_t)b * SS + s);

        // prefetch step-constant operands (independent of h/c)
        float tfv = __ldg(g_tf + bsoff * DD + j);
        const float* uxr = g_ux + bsoff * G4D;
        float ux0 = __ldg(uxr + 0*DD + j);
        float ux1 = __ldg(uxr + 1*DD + j);
        float ux2 = __ldg(uxr + 2*DD + j);
        float ux3 = __ldg(uxr + 3*DD + j);

        // prefetch chunk 0 of h,c (L2 path — L1 is stale across steps)
        float4 ph[4], pc[4];
#pragma unroll
        for (int i = 0; i < 4; i++) {
            int fi = t + i*256; int bb = fi >> 4, k4 = fi & 15;
            ph[i] = __ldcg((const float4*)(h_in + bb*DD + k4*4));
            pc[i] = __ldcg((const float4*)(c_in + bb*DD + k4*4));
        }

        unsigned long long accd = 0ull, acc[4] = {0ull, 0ull, 0ull, 0ull};
        float cprev = 0.0f;

        for (int ch = 0; ch < 8; ch++) {
            __syncthreads();   // prev chunk compute done
#pragma unroll
            for (int i = 0; i < 4; i++) {
                int fi = t + i*256; int bb = fi >> 4, k4 = fi & 15;
                *(float4*)(HS + bb*HPAD + k4*4) = ph[i];
                *(float4*)(CS + bb*HPAD + k4*4) = pc[i];
            }
            __syncthreads();
            if (ch == cchunk) cprev = CSrow[cidx];
            if (ch < 7) {
#pragma unroll
                for (int i = 0; i < 4; i++) {
                    int fi = t + i*256; int bb = fi >> 4, k4 = fi & 15;
                    ph[i] = __ldcg((const float4*)(h_in + bb*DD + (ch+1)*64 + k4*4));
                    pc[i] = __ldcg((const float4*)(c_in + bb*DD + (ch+1)*64 + k4*4));
                }
            }
            int wo = ch * 64;
#pragma unroll
            for (int k4 = 0; k4 < 16; k4++) {
                F4U hv, cv, wd, w0, w1, w2, w3;
                hv.f = *(const float4*)(HSrow + k4*4);
                cv.f = *(const float4*)(CSrow + k4*4);
                wd.f = *(const float4*)(WDrow  + wo + k4*4);
                w0.f = *(const float4*)(WArow0 + wo + k4*4);
                w1.f = *(const float4*)(WArow1 + wo + k4*4);
                w2.f = *(const float4*)(WArow2 + wo + k4*4);
                w3.f = *(const float4*)(WArow3 + wo + k4*4);
                accd   = ffma2(cv.u[0], wd.u[0], accd);
                accd   = ffma2(cv.u[1], wd.u[1], accd);
                acc[0] = ffma2(hv.u[0], w0.u[0], acc[0]);
                acc[0] = ffma2(hv.u[1], w0.u[1], acc[0]);
                acc[1] = ffma2(hv.u[0], w1.u[0], acc[1]);
                acc[1] = ffma2(hv.u[1], w1.u[1], acc[1]);
                acc[2] = ffma2(hv.u[0], w2.u[0], acc[2]);
                acc[2] = ffma2(hv.u[1], w2.u[1], acc[2]);
                acc[3] = ffma2(hv.u[0], w3.u[0], acc[3]);
                acc[3] = ffma2(hv.u[1], w3.u[1], acc[3]);
            }
        }

        // elementwise LSTM update for (b, j)
        float2 vd = unpack2(accd);
        float cs1 = tanhf(vd.x + vd.y + wdb);
        float2 v0 = unpack2(acc[0]);
        float2 v1 = unpack2(acc[1]);
        float2 v2 = unpack2(acc[2]);
        float2 v3 = unpack2(acc[3]);
        float fg = sigmoidf_(v0.x + v0.y + wab0 + ux0);
        float ig = sigmoidf_(v1.x + v1.y + wab1 + ux1);
        float og = sigmoidf_(v2.x + v2.y + wab2 + ux2);
        float ct = sigmoidf_(v3.x + v3.y + wab3 + ux3);

        float cadj  = cprev + cs1 * (tfv - 1.0f);
        float cn    = fg * cadj + ig * ct;
        float hn    = og * tanhf(cn);
        c_out[b*DD + j] = cn;
        h_out[b*DD + j] = hn;
        g_hs[bsoff * DD + j] = hn;

        // ---- grid barrier (phased monotonic counter) ----
        if (s < SS - 1) {
            __syncthreads();
            if (t == 0) {
                __threadfence();                 // release h_out/c_out
                atomicAdd(&g_bar, 1u);
                unsigned target = (unsigned)NCTA * (unsigned)(s + 1);
                while (*(volatile unsigned*)&g_bar < target) { __nanosleep(64); }
                __threadfence();                 // acquire + L1 invalidate
            }
            __syncthreads();
        }
    }
}

// ---------------- kernel: max-pool over S + output head ------------------------
__global__ __launch_bounds__(512) void k_pool(const float* __restrict__ ow,
                                              const float* __restrict__ ob,
                                              float* __restrict__ out) {
    int b = blockIdx.x;
    int d = threadIdx.x;
    const float* p = g_hs + (size_t)b * SS * DD + d;
    float m = -3.0e38f;
#pragma unroll 8
    for (int s = 0; s < SS; s++) m = fmaxf(m, p[(size_t)s * DD]);
    float s0 = m * ow[d];
    float s1 = m * ow[DD + d];
    __shared__ float r0[512], r1[512];
    r0[d] = s0; r1[d] = s1;
    __syncthreads();
    for (int off = 256; off > 0; off >>= 1) {
        if (d < off) { r0[d] += r0[d + off]; r1[d] += r1[d + off]; }
        __syncthreads();
    }
    if (d == 0) {
        out[b*2 + 0] = r0[0] + ob[0];
        out[b*2 + 1] = r1[0] + ob[1];
    }
}

// ---------------- launch --------------------------------------------------------
extern "C" void kernel_launch(void* const* d_in, const int* in_sizes, int n_in,
                              void* d_out, int out_size) {
    const float* emb   = (const float*)d_in[0];
    const float* Wall  = (const float*)d_in[1];
    const float* Wallb = (const float*)d_in[2];
    const float* U     = (const float*)d_in[3];
    const float* Ub    = (const float*)d_in[4];
    const float* Wd    = (const float*)d_in[5];
    const float* Wdb   = (const float*)d_in[6];
    const float* selw  = (const float*)d_in[7];
    const float* selb  = (const float*)d_in[8];
    const float* timew = (const float*)d_in[9];
    const float* timeb = (const float*)d_in[10];
    const float* outw  = (const float*)d_in[11];
    const float* outb  = (const float*)d_in[12];
    const float* tstep = (const float*)d_in[13];
    const int*   seqs  = (const int*)d_in[14];
    float* out = (float*)d_out;

    static int configured = 0;
    if (!configured) {
        cudaFuncSetAttribute(k_rnn, cudaFuncAttributeMaxDynamicSharedMemorySize, STEP_SMEM);
        configured = 1;
    }

    k_zero<<<128, 256>>>();
    k_gather<<<BS, 128>>>(emb, seqs);
    k_tf<<<128, 512>>>(tstep, selw, selb, timew, timeb);
    k_gemm_ux<<<dim3(G4D/TN, BS/TM), 256>>>(U, Ub);
    k_rnn<<<NCTA, 256, STEP_SMEM>>>(Wall, Wallb, Wd, Wdb);
    k_pool<<<BB, 512>>>(outw, outb, out);
}